// round 2
// baseline (speedup 1.0000x reference)
#include <cuda_runtime.h>

// BilinearChebConv: out[o] = sum_{i,j} theta[i,j,o] * (Tr[i] @ X @ Tc[j]) + bias[o]
// M = N = 1536, P_ROW = P_COL = 4, OUT = 32. All fp32.

constexpr int NM = 1536;
constexpr int N2 = NM * NM;          // 2359296
constexpr int BM = 128, BN = 128, BK = 16;
constexpr int NKT = NM / BK;         // 96
constexpr int OUTC = 32;

// Scratch planes (no cudaMalloc allowed): 30 * 9.44 MB = ~283 MB
__device__ float g_Tr[3][N2];   // T2, T3, T4 (row side)
__device__ float g_Tc[3][N2];   // T2, T3, T4 (col side)
__device__ float g_Y[4][N2];    // Y[i] = Tr[i] @ X, i = 1..4   (Y[0] = X)
__device__ float g_Z[20][N2];   // Z[i][j] = Y[i] @ Tc[j], i=0..4, j=1..4, idx = i*4+(j-1)

// ---------------------------------------------------------------------------
// Core 128x128x16 fp32 GEMM mainloop, double-buffered smem, 8x8 per thread.
// Grid (12,12,*), block 256. Fills acc[8][8]; epilogue is per-kernel.
// ---------------------------------------------------------------------------
__device__ __forceinline__ void gemm_core(const float* __restrict__ A,
                                          const float* __restrict__ B,
                                          float (&acc)[8][8])
{
    __shared__ float As[2][BK][BM + 4];   // padded to soften store conflicts
    __shared__ float Bs[2][BK][BN];

    const int tid = threadIdx.x;
    const int bm = blockIdx.y * BM;
    const int bn = blockIdx.x * BN;

    // A tile: 128 rows x 16 cols -> 512 float4, 2 per thread
    const int arow = tid >> 2;            // 0..63 (and +64)
    const int acol = (tid & 3) << 2;      // 0,4,8,12
    // B tile: 16 rows x 128 cols -> 512 float4, 2 per thread
    const int brow = tid >> 5;            // 0..7 (and +8)
    const int bcol = (tid & 31) << 2;     // 0..124

    const float* Ap0 = A + (bm + arow) * NM + acol;
    const float* Ap1 = Ap0 + 64 * NM;
    const float* Bp0 = B + brow * NM + bn + bcol;
    const float* Bp1 = Bp0 + 8 * NM;

    float4 a0 = *(const float4*)Ap0;
    float4 a1 = *(const float4*)Ap1;
    float4 b0 = *(const float4*)Bp0;
    float4 b1 = *(const float4*)Bp1;

    // store tile 0 (A transposed into As[k][m])
    As[0][acol + 0][arow] = a0.x; As[0][acol + 1][arow] = a0.y;
    As[0][acol + 2][arow] = a0.z; As[0][acol + 3][arow] = a0.w;
    As[0][acol + 0][arow + 64] = a1.x; As[0][acol + 1][arow + 64] = a1.y;
    As[0][acol + 2][arow + 64] = a1.z; As[0][acol + 3][arow + 64] = a1.w;
    *(float4*)&Bs[0][brow][bcol]     = b0;
    *(float4*)&Bs[0][brow + 8][bcol] = b1;
    __syncthreads();

    const int tm = (tid >> 4) << 2;       // 0..60
    const int tn = (tid & 15) << 2;       // 0..60

    for (int kt = 0; kt < NKT; ++kt) {
        const int cur = kt & 1;
        if (kt + 1 < NKT) {
            const int k0 = (kt + 1) * BK;
            a0 = *(const float4*)(Ap0 + k0);
            a1 = *(const float4*)(Ap1 + k0);
            b0 = *(const float4*)(Bp0 + k0 * NM);
            b1 = *(const float4*)(Bp1 + k0 * NM);
        }
#pragma unroll
        for (int k = 0; k < BK; ++k) {
            float ra[8], rb[8];
            *(float4*)(ra)     = *(const float4*)&As[cur][k][tm];
            *(float4*)(ra + 4) = *(const float4*)&As[cur][k][tm + 64];
            *(float4*)(rb)     = *(const float4*)&Bs[cur][k][tn];
            *(float4*)(rb + 4) = *(const float4*)&Bs[cur][k][tn + 64];
#pragma unroll
            for (int i = 0; i < 8; ++i)
#pragma unroll
                for (int j = 0; j < 8; ++j)
                    acc[i][j] += ra[i] * rb[j];
        }
        if (kt + 1 < NKT) {
            const int nxt = cur ^ 1;
            As[nxt][acol + 0][arow] = a0.x; As[nxt][acol + 1][arow] = a0.y;
            As[nxt][acol + 2][arow] = a0.z; As[nxt][acol + 3][arow] = a0.w;
            As[nxt][acol + 0][arow + 64] = a1.x; As[nxt][acol + 1][arow + 64] = a1.y;
            As[nxt][acol + 2][arow + 64] = a1.z; As[nxt][acol + 3][arow + 64] = a1.w;
            *(float4*)&Bs[nxt][brow][bcol]     = b0;
            *(float4*)&Bs[nxt][brow + 8][bcol] = b1;
        }
        __syncthreads();
    }
}

// epilogues --------------------------------------------------------------
__device__ __forceinline__ void epi_plain(float (&acc)[8][8], float* __restrict__ C)
{
    const int tid = threadIdx.x;
    const int bm = blockIdx.y * BM, bn = blockIdx.x * BN;
    const int tm = (tid >> 4) << 2, tn = (tid & 15) << 2;
#pragma unroll
    for (int i = 0; i < 8; ++i) {
        const int grow = bm + tm + (i & 3) + ((i >> 2) << 6);
#pragma unroll
        for (int cj = 0; cj < 2; ++cj) {
            const int gcol = bn + tn + (cj << 6);
            float4 r = make_float4(acc[i][cj * 4 + 0], acc[i][cj * 4 + 1],
                                   acc[i][cj * 4 + 2], acc[i][cj * 4 + 3]);
            *(float4*)(C + grow * NM + gcol) = r;
        }
    }
}

// C = 2*acc - D
__device__ __forceinline__ void epi_cheb(float (&acc)[8][8],
                                         const float* __restrict__ D,
                                         float* __restrict__ C)
{
    const int tid = threadIdx.x;
    const int bm = blockIdx.y * BM, bn = blockIdx.x * BN;
    const int tm = (tid >> 4) << 2, tn = (tid & 15) << 2;
#pragma unroll
    for (int i = 0; i < 8; ++i) {
        const int grow = bm + tm + (i & 3) + ((i >> 2) << 6);
#pragma unroll
        for (int cj = 0; cj < 2; ++cj) {
            const int gcol = bn + tn + (cj << 6);
            float4 d = *(const float4*)(D + grow * NM + gcol);
            float4 r = make_float4(2.f * acc[i][cj * 4 + 0] - d.x,
                                   2.f * acc[i][cj * 4 + 1] - d.y,
                                   2.f * acc[i][cj * 4 + 2] - d.z,
                                   2.f * acc[i][cj * 4 + 3] - d.w);
            *(float4*)(C + grow * NM + gcol) = r;
        }
    }
}

// C = 2*acc - I
__device__ __forceinline__ void epi_cheb_i(float (&acc)[8][8], float* __restrict__ C)
{
    const int tid = threadIdx.x;
    const int bm = blockIdx.y * BM, bn = blockIdx.x * BN;
    const int tm = (tid >> 4) << 2, tn = (tid & 15) << 2;
#pragma unroll
    for (int i = 0; i < 8; ++i) {
        const int grow = bm + tm + (i & 3) + ((i >> 2) << 6);
#pragma unroll
        for (int cj = 0; cj < 2; ++cj) {
            const int gcol = bn + tn + (cj << 6);
            float4 r;
            r.x = 2.f * acc[i][cj * 4 + 0] - ((grow == gcol + 0) ? 1.f : 0.f);
            r.y = 2.f * acc[i][cj * 4 + 1] - ((grow == gcol + 1) ? 1.f : 0.f);
            r.z = 2.f * acc[i][cj * 4 + 2] - ((grow == gcol + 2) ? 1.f : 0.f);
            r.w = 2.f * acc[i][cj * 4 + 3] - ((grow == gcol + 3) ? 1.f : 0.f);
            *(float4*)(C + grow * NM + gcol) = r;
        }
    }
}

// kernels ----------------------------------------------------------------

// Chebyshev step. which: 0 = row side (g_Tr), 1 = col side (g_Tc).
// step 0: T2 = 2*L@L  - I
// step 1: T3 = 2*L@T2 - L
// step 2: T4 = 2*L@T3 - T2
__global__ void __launch_bounds__(256, 2)
k_cheb(const float* __restrict__ L, int step, int which)
{
    float (*P)[N2] = which ? g_Tc : g_Tr;
    const float* Bm = (step == 0) ? L : P[step - 1];
    float acc[8][8] = {};
    gemm_core(L, Bm, acc);
    if (step == 0)      epi_cheb_i(acc, P[0]);
    else if (step == 1) epi_cheb(acc, L, P[1]);
    else                epi_cheb(acc, P[0], P[2]);
}

// Y[z+1] = Tr[z+1] @ X, z = 0..3 (batched over blockIdx.z)
__global__ void __launch_bounds__(256, 2)
k_gemm_y(const float* __restrict__ Lr, const float* __restrict__ x)
{
    const int z = blockIdx.z;
    const float* A = (z == 0) ? Lr : g_Tr[z - 1];
    float acc[8][8] = {};
    gemm_core(A, x, acc);
    epi_plain(acc, g_Y[z]);
}

// Z[i][j] = Y[i] @ Tc[j], z = i*4 + (j-1), i=0..4, j=1..4 (batched)
__global__ void __launch_bounds__(256, 2)
k_gemm_z(const float* __restrict__ x, const float* __restrict__ Lc)
{
    const int z = blockIdx.z;
    const int i = z >> 2;
    const int jm1 = z & 3;
    const float* A = (i == 0) ? x : g_Y[i - 1];
    const float* B = (jm1 == 0) ? Lc : g_Tc[jm1 - 1];
    float acc[8][8] = {};
    gemm_core(A, B, acc);
    epi_plain(acc, g_Z[z]);
}

// out[o,m,n] = bias[o] + sum_t theta[t*32+o] * v_t[m,n], t = i*5+j
__global__ void __launch_bounds__(256)
k_mix(const float* __restrict__ x, const float* __restrict__ theta,
      const float* __restrict__ bias, float* __restrict__ out)
{
    __shared__ float sh_th[25 * OUTC];
    __shared__ float sh_b[OUTC];
    const int tid = threadIdx.x;
    for (int t = tid; t < 25 * OUTC; t += 256) sh_th[t] = theta[t];
    if (tid < OUTC) sh_b[tid] = bias[tid];
    __syncthreads();

    const int pos2 = blockIdx.x * 256 + tid;    // float2 index
    const int off = pos2 * 2;                   // element index < N2

    float2 v[25];
    v[0] = *(const float2*)(x + off);
#pragma unroll
    for (int i = 1; i <= 4; ++i)
        v[i * 5] = *(const float2*)(g_Y[i - 1] + off);
#pragma unroll
    for (int i = 0; i <= 4; ++i)
#pragma unroll
        for (int j = 1; j <= 4; ++j)
            v[i * 5 + j] = *(const float2*)(g_Z[i * 4 + (j - 1)] + off);

#pragma unroll
    for (int o = 0; o < OUTC; ++o) {
        float sx = sh_b[o], sy = sh_b[o];
#pragma unroll
        for (int t = 0; t < 25; ++t) {
            const float w = sh_th[t * OUTC + o];
            sx += w * v[t].x;
            sy += w * v[t].y;
        }
        *(float2*)(out + (size_t)o * N2 + off) = make_float2(sx, sy);
    }
}

// ---------------------------------------------------------------------------
extern "C" void kernel_launch(void* const* d_in, const int* in_sizes, int n_in,
                              void* d_out, int out_size)
{
    const float* x     = (const float*)d_in[0];   // (1,1536,1536)
    const float* Lr    = (const float*)d_in[1];   // (1536,1536)
    const float* Lc    = (const float*)d_in[2];   // (1536,1536)
    const float* theta = (const float*)d_in[3];   // (5,5,1,32)
    const float* bias  = (const float*)d_in[4];   // (32,)
    float* out = (float*)d_out;                   // (32,1536,1536)

    const dim3 blk(256);
    const dim3 g2(NM / BN, NM / BM, 1);           // (12,12)

    // Chebyshev bases (3 GEMMs per side, sequential dependencies)
    k_cheb<<<g2, blk>>>(Lr, 0, 0);
    k_cheb<<<g2, blk>>>(Lr, 1, 0);
    k_cheb<<<g2, blk>>>(Lr, 2, 0);
    k_cheb<<<g2, blk>>>(Lc, 0, 1);
    k_cheb<<<g2, blk>>>(Lc, 1, 1);
    k_cheb<<<g2, blk>>>(Lc, 2, 1);

    // Y[i] = Tr[i] @ X (4 GEMMs, batched)
    k_gemm_y<<<dim3(12, 12, 4), blk>>>(Lr, x);

    // Z[i][j] = Y[i] @ Tc[j] (20 GEMMs, batched)
    k_gemm_z<<<dim3(12, 12, 20), blk>>>(x, Lc);

    // Final 25-term mix into 32 channels + bias
    k_mix<<<N2 / 2 / 256, blk>>>(x, theta, bias, out);
}

// round 4
// speedup vs baseline: 2.0636x; 2.0636x over previous
#include <cuda_runtime.h>
#include <cuda_fp16.h>
#include <cstdint>

// ============================================================================
// BilinearChebConv via mma.sync (fp16 3-way split GEMMs, fp32 accumulate)
// out[o] = sum_{i,j} theta[i,j,o] * (Tr_i @ X @ Tc_j) + bias[o]
// M = N = 1536, orders 4/4, OUT = 32.  Plain sm_103-target PTX only
// (mma.sync / ldmatrix / cp.async) -- tcgen05 unavailable at this target.
// ============================================================================

constexpr int NM   = 1536;
constexpr int N2   = NM * NM;
constexpr int OUTC = 32;

constexpr int BK   = 64;                 // k per stage (64 fp16 = 128B row)
constexpr int NKT  = NM / BK;            // 24
constexpr int PLANE = 128 * 128;         // bytes per operand plane per stage
constexpr int STAGE = 4 * PLANE;         // Ah|Al|Bh|Bl = 64 KB
constexpr unsigned SMEM_DYN = 2 * STAGE; // 128 KB

// ----------------------------------------------------------------------------
// Scratch (no cudaMalloc allowed -> __device__ globals)
__device__ float g_Tr32[3][N2];
__device__ float g_Tc32[3][N2];
__device__ float g_W32[4][N2];          // W_j = X @ Tc_j      (= Z_{0,j})
__device__ float g_Y32[4][N2];          // Y_i = Tr_i @ X      (= Z_{i,0})
__device__ float g_Z32[16][N2];         // Z_ij = Tr_i @ W_j,  i,j = 1..4
// fp16 hi/lo operand planes (all B operands stored as N x K)
__device__ __half g_Xh[N2],  g_Xl[N2];      // X   (A operand, row-major)
__device__ __half g_XTh[N2], g_XTl[N2];     // X^T (B operand for Y-stage)
__device__ __half g_Lrh[N2], g_Lrl[N2];
__device__ __half g_Lch[N2], g_Lcl[N2];
__device__ __half g_Trh[3][N2], g_Trl[3][N2];   // symmetric -> B directly
__device__ __half g_Tch[3][N2], g_Tcl[3][N2];
__device__ __half g_WTh[4][N2], g_WTl[4][N2];   // W_j^T (B for Z-stage)

// ----------------------------------------------------------------------------
// PTX helpers (all baseline sm_80+ instructions)
// ----------------------------------------------------------------------------
__device__ __forceinline__ uint32_t smem_u32(const void* p) {
    uint32_t a;
    asm("{ .reg .u64 t; cvta.to.shared.u64 t, %1; cvt.u32.u64 %0, t; }"
        : "=r"(a) : "l"(p));
    return a;
}
__device__ __forceinline__ void cpa16(uint32_t s, const void* g) {
    asm volatile("cp.async.cg.shared.global [%0], [%1], 16;\n" :: "r"(s), "l"(g));
}
__device__ __forceinline__ void cp_commit() {
    asm volatile("cp.async.commit_group;\n" ::: "memory");
}
__device__ __forceinline__ void cp_wait1() {
    asm volatile("cp.async.wait_group 1;\n" ::: "memory");
}
__device__ __forceinline__ void ldsm4(uint32_t* r, uint32_t a) {
    asm volatile("ldmatrix.sync.aligned.m8n8.x4.shared.b16 {%0,%1,%2,%3}, [%4];"
                 : "=r"(r[0]), "=r"(r[1]), "=r"(r[2]), "=r"(r[3]) : "r"(a));
}
__device__ __forceinline__ void mma16816(float* c, const uint32_t* a,
                                         uint32_t b0, uint32_t b1) {
    asm volatile("mma.sync.aligned.m16n8k16.row.col.f32.f16.f16.f32 "
                 "{%0,%1,%2,%3}, {%4,%5,%6,%7}, {%8,%9}, {%0,%1,%2,%3};"
                 : "+f"(c[0]), "+f"(c[1]), "+f"(c[2]), "+f"(c[3])
                 : "r"(a[0]), "r"(a[1]), "r"(a[2]), "r"(a[3]), "r"(b0), "r"(b1));
}

// ----------------------------------------------------------------------------
// Core GEMM: C(128x128) += 3-split product over K=1536.
// Block = 256 threads, 8 warps of 64x32. acc[4][4][4] per thread.
// Smem rows are 128B with SW128 xor swizzle -> conflict-free ldmatrix.
// ----------------------------------------------------------------------------
__device__ __forceinline__ void gemm_main(
    const __half* __restrict__ Ah, const __half* __restrict__ Al,
    const __half* __restrict__ Bh, const __half* __restrict__ Bl,
    float (&acc)[4][4][4])
{
    extern __shared__ char dsm[];
    const uint32_t sbase = smem_u32(dsm);
    const int tid = threadIdx.x, lane = tid & 31, wid = tid >> 5;
    const int wm = (wid & 1) * 64, wn = (wid >> 1) * 32;
    const int l15 = lane & 15, lhi = lane >> 4;
    const int bm = blockIdx.y * 128, bn = blockIdx.x * 128;
    const int lc = tid & 7, lr = tid >> 3;     // loader: chunk 0..7, row 0..31

    auto load_stage = [&](int st, int kc) {
        const uint32_t sb = sbase + st * STAGE;
#pragma unroll
        for (int rr = 0; rr < 128; rr += 32) {
            const int r = lr + rr;
            const uint32_t off = (uint32_t)(r * 128) + (uint32_t)((lc ^ (r & 7)) << 4);
            const size_t ga = (size_t)(bm + r) * NM + kc + lc * 8;
            const size_t gb = (size_t)(bn + r) * NM + kc + lc * 8;
            cpa16(sb + 0 * PLANE + off, Ah + ga);
            cpa16(sb + 1 * PLANE + off, Al + ga);
            cpa16(sb + 2 * PLANE + off, Bh + gb);
            cpa16(sb + 3 * PLANE + off, Bl + gb);
        }
    };

    load_stage(0, 0);  cp_commit();
    load_stage(1, BK); cp_commit();

    for (int kt = 0; kt < NKT; ++kt) {
        cp_wait1();
        __syncthreads();
        const uint32_t sb = sbase + (kt & 1) * STAGE;
#pragma unroll
        for (int kh = 0; kh < 4; ++kh) {               // four k16 slices per stage
            uint32_t ahf[4][4], alf[4][4], bhf[2][4], blf[2][4];
            const int chunkL = (kh << 1) | lhi;        // logical 16B chunk
#pragma unroll
            for (int mt = 0; mt < 4; ++mt) {
                const int r = wm + mt * 16 + l15;
                const uint32_t off = (uint32_t)(r * 128) +
                                     (uint32_t)((chunkL ^ (r & 7)) << 4);
                ldsm4(ahf[mt], sb + 0 * PLANE + off);
                ldsm4(alf[mt], sb + 1 * PLANE + off);
            }
#pragma unroll
            for (int g = 0; g < 2; ++g) {
                const int r = wn + g * 16 + l15;
                const uint32_t off = (uint32_t)(r * 128) +
                                     (uint32_t)((chunkL ^ (r & 7)) << 4);
                ldsm4(bhf[g], sb + 2 * PLANE + off);
                ldsm4(blf[g], sb + 3 * PLANE + off);
            }
#pragma unroll
            for (int mt = 0; mt < 4; ++mt)
#pragma unroll
                for (int nt = 0; nt < 4; ++nt) {
                    const int g = nt >> 1, j = nt & 1;
                    mma16816(acc[mt][nt], ahf[mt], bhf[g][j], bhf[g][j + 2]);
                    mma16816(acc[mt][nt], alf[mt], bhf[g][j], bhf[g][j + 2]);
                    mma16816(acc[mt][nt], ahf[mt], blf[g][j], blf[g][j + 2]);
                }
        }
        __syncthreads();
        if (kt + 2 < NKT) load_stage(kt & 1, (kt + 2) * BK);
        cp_commit();
    }
}

// plain fp32 epilogue -------------------------------------------------------
__device__ __forceinline__ void epi_plain(float (&acc)[4][4][4], float* __restrict__ C)
{
    const int tid = threadIdx.x, lane = tid & 31, wid = tid >> 5;
    const int wm = (wid & 1) * 64, wn = (wid >> 1) * 32;
    const int bm = blockIdx.y * 128, bn = blockIdx.x * 128;
    const int l4 = lane >> 2, l2 = (lane & 3) * 2;
#pragma unroll
    for (int mt = 0; mt < 4; ++mt)
#pragma unroll
        for (int h = 0; h < 2; ++h) {
            const int row = bm + wm + mt * 16 + l4 + h * 8;
#pragma unroll
            for (int nt = 0; nt < 4; ++nt) {
                const int col = bn + wn + nt * 8 + l2;
                *(float2*)(C + (size_t)row * NM + col) =
                    make_float2(acc[mt][nt][2 * h], acc[mt][nt][2 * h + 1]);
            }
        }
}

// ----------------------------------------------------------------------------
// Kernels
// ----------------------------------------------------------------------------

// Chebyshev step: T_step = 2 * L @ B - D. Writes fp32 + fp16 hi/lo (symmetric,
// so the row-major result doubles as the N x K B-operand).
__global__ void __launch_bounds__(256)
k_gemm_cheb(const float* __restrict__ L32, int side, int step)
{
    const __half* Ah = side ? g_Lch : g_Lrh;
    const __half* Al = side ? g_Lcl : g_Lrl;
    const __half* Bh = (step == 0) ? Ah : (side ? g_Tch[step - 1] : g_Trh[step - 1]);
    const __half* Bl = (step == 0) ? Al : (side ? g_Tcl[step - 1] : g_Trl[step - 1]);
    const float* D = (step == 0) ? nullptr
                   : (step == 1) ? L32
                   : (side ? g_Tc32[0] : g_Tr32[0]);
    float* C = side ? g_Tc32[step] : g_Tr32[step];
    __half* Ho = side ? g_Tch[step] : g_Trh[step];
    __half* Lo = side ? g_Tcl[step] : g_Trl[step];

    float acc[4][4][4] = {};
    gemm_main(Ah, Al, Bh, Bl, acc);

    const int tid = threadIdx.x, lane = tid & 31, wid = tid >> 5;
    const int wm = (wid & 1) * 64, wn = (wid >> 1) * 32;
    const int bm = blockIdx.y * 128, bn = blockIdx.x * 128;
    const int l4 = lane >> 2, l2 = (lane & 3) * 2;
#pragma unroll
    for (int mt = 0; mt < 4; ++mt)
#pragma unroll
        for (int h = 0; h < 2; ++h) {
            const int row = bm + wm + mt * 16 + l4 + h * 8;
#pragma unroll
            for (int nt = 0; nt < 4; ++nt) {
                const int col = bn + wn + nt * 8 + l2;
                const size_t off = (size_t)row * NM + col;
                float2 d;
                if (D) d = *(const float2*)(D + off);
                else   d = make_float2(row == col ? 1.f : 0.f,
                                       row == col + 1 ? 1.f : 0.f);
                const float vx = 2.f * acc[mt][nt][2 * h]     - d.x;
                const float vy = 2.f * acc[mt][nt][2 * h + 1] - d.y;
                *(float2*)(C + off) = make_float2(vx, vy);
                const __half hx = __float2half_rn(vx);
                const __half hy = __float2half_rn(vy);
                __half2 p;
                p.x = hx; p.y = hy;
                *(__half2*)(Ho + off) = p;
                p.x = __float2half_rn(vx - __half2float(hx));
                p.y = __float2half_rn(vy - __half2float(hy));
                *(__half2*)(Lo + off) = p;
            }
        }
}

// W_j = X @ Tc_j (j-1 = blockIdx.z); B symmetric.
__global__ void __launch_bounds__(256)
k_gemm_w()
{
    const int z = blockIdx.z;
    const __half* Bh = (z == 0) ? g_Lch : g_Tch[z - 1];
    const __half* Bl = (z == 0) ? g_Lcl : g_Tcl[z - 1];
    float acc[4][4][4] = {};
    gemm_main(g_Xh, g_Xl, Bh, Bl, acc);
    epi_plain(acc, g_W32[z]);
}

// Y_i = Tr_i @ X (i-1 = blockIdx.z); B = X^T planes.
__global__ void __launch_bounds__(256)
k_gemm_y()
{
    const int z = blockIdx.z;
    const __half* Ah = (z == 0) ? g_Lrh : g_Trh[z - 1];
    const __half* Al = (z == 0) ? g_Lrl : g_Trl[z - 1];
    float acc[4][4][4] = {};
    gemm_main(Ah, Al, g_XTh, g_XTl, acc);
    epi_plain(acc, g_Y32[z]);
}

// Z_ij = Tr_i @ W_j; z = (i-1)*4 + (j-1); B = W_j^T planes.
__global__ void __launch_bounds__(256)
k_gemm_z()
{
    const int z = blockIdx.z;
    const int i = z >> 2, j = z & 3;
    const __half* Ah = (i == 0) ? g_Lrh : g_Trh[i - 1];
    const __half* Al = (i == 0) ? g_Lrl : g_Trl[i - 1];
    float acc[4][4][4] = {};
    gemm_main(Ah, Al, g_WTh[j], g_WTl[j], acc);
    epi_plain(acc, g_Z32[z]);
}

// ----------------------------------------------------------------------------
// fp32 -> fp16 hi/lo conversion of inputs (z: 0=X, 1=Lr, 2=Lc)
__global__ void __launch_bounds__(256)
k_cvt(const float* __restrict__ x, const float* __restrict__ Lr,
      const float* __restrict__ Lc)
{
    const int zz = blockIdx.z;
    const float* s = (zz == 0) ? x : (zz == 1) ? Lr : Lc;
    __half* H = (zz == 0) ? g_Xh : (zz == 1) ? g_Lrh : g_Lch;
    __half* L = (zz == 0) ? g_Xl : (zz == 1) ? g_Lrl : g_Lcl;
    const int i = (blockIdx.x * 256 + threadIdx.x) * 4;
    float4 v = *(const float4*)(s + i);
    __half h0 = __float2half_rn(v.x), h1 = __float2half_rn(v.y);
    __half h2 = __float2half_rn(v.z), h3 = __float2half_rn(v.w);
    __half2 p;
    p.x = h0; p.y = h1; *(__half2*)(H + i)     = p;
    p.x = h2; p.y = h3; *(__half2*)(H + i + 2) = p;
    p.x = __float2half_rn(v.x - __half2float(h0));
    p.y = __float2half_rn(v.y - __half2float(h1));
    *(__half2*)(L + i) = p;
    p.x = __float2half_rn(v.z - __half2float(h2));
    p.y = __float2half_rn(v.w - __half2float(h3));
    *(__half2*)(L + i + 2) = p;
}

// X^T hi/lo
__global__ void __launch_bounds__(256)
k_cvtT(const float* __restrict__ X)
{
    __shared__ float t[32][33];
    const int tx = threadIdx.x, ty = threadIdx.y;
    const int n0 = blockIdx.x * 32, m0 = blockIdx.y * 32;
#pragma unroll
    for (int i = 0; i < 4; ++i)
        t[ty + 8 * i][tx] = X[(size_t)(m0 + ty + 8 * i) * NM + n0 + tx];
    __syncthreads();
#pragma unroll
    for (int i = 0; i < 4; ++i) {
        const int nl = ty + 8 * i;
        const float v = t[tx][nl];                    // X[m0+tx][n0+nl]
        const size_t off = (size_t)(n0 + nl) * NM + m0 + tx;
        __half h = __float2half_rn(v);
        g_XTh[off] = h;
        g_XTl[off] = __float2half_rn(v - __half2float(h));
    }
}

// W^T hi/lo (z = j-1)
__global__ void __launch_bounds__(256)
k_trW()
{
    const int z = blockIdx.z;
    const float* S = g_W32[z];
    __half* TH = g_WTh[z];
    __half* TL = g_WTl[z];
    __shared__ float t[32][33];
    const int tx = threadIdx.x, ty = threadIdx.y;
    const int n0 = blockIdx.x * 32, m0 = blockIdx.y * 32;
#pragma unroll
    for (int i = 0; i < 4; ++i)
        t[ty + 8 * i][tx] = S[(size_t)(m0 + ty + 8 * i) * NM + n0 + tx];
    __syncthreads();
#pragma unroll
    for (int i = 0; i < 4; ++i) {
        const int nl = ty + 8 * i;
        const float v = t[tx][nl];
        const size_t off = (size_t)(n0 + nl) * NM + m0 + tx;
        __half h = __float2half_rn(v);
        TH[off] = h;
        TL[off] = __float2half_rn(v - __half2float(h));
    }
}

// ----------------------------------------------------------------------------
// Final mix: out[o,m,n] = bias[o] + sum_t theta[t,o] * plane_t[m,n]
__global__ void __launch_bounds__(256)
k_mix(const float* __restrict__ x, const float* __restrict__ theta,
      const float* __restrict__ bias, float* __restrict__ out)
{
    __shared__ float sh_th[25 * OUTC];
    __shared__ float sh_b[OUTC];
    const int tid = threadIdx.x;
    for (int t = tid; t < 25 * OUTC; t += 256) sh_th[t] = theta[t];
    if (tid < OUTC) sh_b[tid] = bias[tid];
    __syncthreads();

    const int off = (blockIdx.x * 256 + tid) * 2;

    float2 v[25];
    v[0] = *(const float2*)(x + off);
#pragma unroll
    for (int j = 1; j <= 4; ++j) v[j] = *(const float2*)(g_W32[j - 1] + off);
#pragma unroll
    for (int i = 1; i <= 4; ++i) v[i * 5] = *(const float2*)(g_Y32[i - 1] + off);
#pragma unroll
    for (int i = 1; i <= 4; ++i)
#pragma unroll
        for (int j = 1; j <= 4; ++j)
            v[i * 5 + j] = *(const float2*)(g_Z32[(i - 1) * 4 + (j - 1)] + off);

#pragma unroll
    for (int o = 0; o < OUTC; ++o) {
        float sx = sh_b[o], sy = sh_b[o];
#pragma unroll
        for (int t = 0; t < 25; ++t) {
            const float w = sh_th[t * OUTC + o];
            sx += w * v[t].x;
            sy += w * v[t].y;
        }
        *(float2*)(out + (size_t)o * N2 + off) = make_float2(sx, sy);
    }
}

// ----------------------------------------------------------------------------
extern "C" void kernel_launch(void* const* d_in, const int* in_sizes, int n_in,
                              void* d_out, int out_size)
{
    const float* x     = (const float*)d_in[0];
    const float* Lr    = (const float*)d_in[1];
    const float* Lc    = (const float*)d_in[2];
    const float* theta = (const float*)d_in[3];
    const float* bias  = (const float*)d_in[4];
    float* out = (float*)d_out;

    static bool attr_done = false;
    if (!attr_done) {
        cudaFuncSetAttribute(k_gemm_cheb, cudaFuncAttributeMaxDynamicSharedMemorySize, SMEM_DYN);
        cudaFuncSetAttribute(k_gemm_w,    cudaFuncAttributeMaxDynamicSharedMemorySize, SMEM_DYN);
        cudaFuncSetAttribute(k_gemm_y,    cudaFuncAttributeMaxDynamicSharedMemorySize, SMEM_DYN);
        cudaFuncSetAttribute(k_gemm_z,    cudaFuncAttributeMaxDynamicSharedMemorySize, SMEM_DYN);
        attr_done = true;
    }

    const dim3 blk(256);
    const dim3 g2(NM / 128, NM / 128, 1);        // (12,12)
    const dim3 blkT(32, 8);
    const dim3 gT(NM / 32, NM / 32, 1);

    // input conversions
    k_cvt<<<dim3(N2 / 1024, 1, 3), blk>>>(x, Lr, Lc);
    k_cvtT<<<gT, blkT>>>(x);

    // Chebyshev bases (sequential per side)
    for (int step = 0; step < 3; ++step)
        k_gemm_cheb<<<g2, blk, SMEM_DYN>>>(Lr, 0, step);
    for (int step = 0; step < 3; ++step)
        k_gemm_cheb<<<g2, blk, SMEM_DYN>>>(Lc, 1, step);

    // W_j = X @ Tc_j
    k_gemm_w<<<dim3(12, 12, 4), blk, SMEM_DYN>>>();
    // W^T hi/lo for the Z-stage B operands
    k_trW<<<dim3(NM / 32, NM / 32, 4), blkT>>>();
    // Y_i = Tr_i @ X
    k_gemm_y<<<dim3(12, 12, 4), blk, SMEM_DYN>>>();
    // Z_ij = Tr_i @ W_j
    k_gemm_z<<<dim3(12, 12, 16), blk, SMEM_DYN>>>();

    // final 25-term mix
    k_mix<<<N2 / 512, blk>>>(x, theta, bias, out);
}